// round 9
// baseline (speedup 1.0000x reference)
#include <cuda_runtime.h>
#include <stdint.h>

#define CC     4
#define INCH   256
#define NT     256
#define SORTN  2048
#define NMAXN  100000
#define NJOBS  256                       // 64 graphs * 4 columns
#define OCC    4

// Scratch (device globals; no allocation allowed)
__device__ float g_xw[NMAXN * CC];
__device__ float g_agg[NMAXN * CC];
__device__ float g_deg[NMAXN];
__device__ float g_dinv[NMAXN];
__device__ int   g_mask[NMAXN];
__device__ unsigned g_bar_cnt;
__device__ volatile unsigned g_bar_gen;

struct TkS  { unsigned u[SORTN]; int hist[256]; int wsum[8]; };
struct XwS  { float pes[INCH]; float4 Wm[INCH]; };
struct OutS { float4 pe[CC * (INCH / 4)]; };
union SmemU { TkS tk; XwS xw; OutS o; };

__device__ __forceinline__ void gbar() {
    __threadfence();
    __syncthreads();
    if (threadIdx.x == 0) {
        unsigned gen = g_bar_gen;
        if (atomicAdd(&g_bar_cnt, 1u) == gridDim.x - 1u) {
            g_bar_cnt = 0u;
            __threadfence();
            g_bar_gen = gen + 1u;
        } else {
            while (g_bar_gen == gen) __nanosleep(32);
        }
    }
    __syncthreads();
}

__device__ __forceinline__ int scan256(int v, int tid, int* wsum) {
    int lane = tid & 31, wid = tid >> 5, orig = v;
#pragma unroll
    for (int o = 1; o < 32; o <<= 1) {
        int t = __shfl_up_sync(0xffffffffu, v, o);
        if (lane >= o) v += t;
    }
    if (lane == 31) wsum[wid] = v;
    __syncthreads();
    if (wid == 0 && lane < 8) {
        int w = wsum[lane];
#pragma unroll
        for (int o = 1; o < 8; o <<= 1) {
            int t = __shfl_up_sync(0xffu, w, o, 8);
            if (lane >= o) w += t;
        }
        wsum[lane] = w;
    }
    __syncthreads();
    return v + (wid ? wsum[wid - 1] : 0) - orig;
}

__global__ void __launch_bounds__(NT, OCC) k_fused(
    const float* __restrict__ x, const int* __restrict__ ei,
    const int* __restrict__ batch, const float* __restrict__ pe,
    const float* __restrict__ W, const float* __restrict__ bb,
    float* __restrict__ out, int n, int E) {
    __shared__ SmemU sm;
    __shared__ int s_p0, s_p1, s_target;
    __shared__ unsigned s_prefix;

    int tid  = threadIdx.x;
    int bid  = blockIdx.x;
    int NB   = gridDim.x;
    int warp = tid >> 5, lane = tid & 31;
    const int* col = ei + E;

    // ===== Phase 1: xw GEMV (2 nodes/warp) + degree atomics, block-stride ===
    for (int t = tid; t < INCH; t += NT) {
        sm.xw.pes[t] = pe[t] + pe[INCH + t] + pe[2 * INCH + t] + pe[3 * INCH + t];
        sm.xw.Wm[t]  = ((const float4*)W)[t];
    }
    __syncthreads();

    int xwU  = (n + 15) >> 4;             // 16 nodes per unit (2 per warp)
    int degU = (E + 1023) >> 10;          // 1024 edges per unit
    for (int v = bid; v < xwU + degU; v += NB) {
        if (v < xwU) {
            int base = v * 16 + warp * 2;
            float4 xv[2][2];
#pragma unroll
            for (int j = 0; j < 2; ++j) {
                int node = (base + j < n) ? base + j : (n - 1);
                const float4* xr = (const float4*)(x + (size_t)node * INCH);
                xv[j][0] = __ldcs(&xr[lane]);
                xv[j][1] = __ldcs(&xr[lane + 32]);
            }
#pragma unroll
            for (int j = 0; j < 2; ++j) {
                float a0 = 0.f, a1 = 0.f, a2 = 0.f, a3 = 0.f;
#pragma unroll
                for (int it = 0; it < 2; ++it) {
                    int k4 = lane + it * 32;
                    float4 q = xv[j][it];
                    int k = k4 * 4;
                    float x0 = q.x + sm.xw.pes[k + 0];
                    float x1 = q.y + sm.xw.pes[k + 1];
                    float x2 = q.z + sm.xw.pes[k + 2];
                    float x3 = q.w + sm.xw.pes[k + 3];
                    float4 w0 = sm.xw.Wm[k + 0], w1 = sm.xw.Wm[k + 1];
                    float4 w2 = sm.xw.Wm[k + 2], w3 = sm.xw.Wm[k + 3];
                    a0 += x0 * w0.x + x1 * w1.x + x2 * w2.x + x3 * w3.x;
                    a1 += x0 * w0.y + x1 * w1.y + x2 * w2.y + x3 * w3.y;
                    a2 += x0 * w0.z + x1 * w1.z + x2 * w2.z + x3 * w3.z;
                    a3 += x0 * w0.w + x1 * w1.w + x2 * w2.w + x3 * w3.w;
                }
#pragma unroll
                for (int o = 16; o; o >>= 1) {
                    a0 += __shfl_xor_sync(0xffffffffu, a0, o);
                    a1 += __shfl_xor_sync(0xffffffffu, a1, o);
                    a2 += __shfl_xor_sync(0xffffffffu, a2, o);
                    a3 += __shfl_xor_sync(0xffffffffu, a3, o);
                }
                if (lane == 0 && base + j < n) {
                    ((float4*)g_xw)[base + j]  = make_float4(a0, a1, a2, a3);
                    ((float4*)g_agg)[base + j] = make_float4(0.f, 0.f, 0.f, 0.f);
                    g_mask[base + j] = 0;
                }
            }
        } else {
            int d = v - xwU;
            int e = d * 1024 + tid;
#pragma unroll
            for (int it = 0; it < 4; ++it) {
                int ee = e + it * 256;
                if (ee < E) atomicAdd(&g_deg[__ldcs(&col[ee])], 1.0f);
            }
        }
    }
    gbar();

    // ===== Phase 2: prep ====================================================
    for (int i = bid * NT + tid; i < n; i += NB * NT) {
        float d = rsqrtf(g_deg[i] + 1.0f);
        g_deg[i]  = 0.0f;
        g_dinv[i] = d;
        float4 v = ((const float4*)g_xw)[i];
        v.x *= d; v.y *= d; v.z *= d; v.w *= d;
        ((float4*)g_xw)[i] = v;
    }
    gbar();

    // ===== Phase 3: edge aggregation ========================================
    {
        int eU = (E + 7) >> 3;
        for (int t = bid * NT + tid; t < eU; t += NB * NT) {
            int base = t * 8;
            if (base + 8 <= E) {
                int4 ra = __ldcs((const int4*)(ei + base));
                int4 rb = __ldcs((const int4*)(ei + base + 4));
                int4 ca = __ldcs((const int4*)(col + base));
                int4 cb = __ldcs((const int4*)(col + base + 4));
                float4 v0 = ((const float4*)g_xw)[ra.x];
                float4 v1 = ((const float4*)g_xw)[ra.y];
                float4 v2 = ((const float4*)g_xw)[ra.z];
                float4 v3 = ((const float4*)g_xw)[ra.w];
                float4 v4 = ((const float4*)g_xw)[rb.x];
                float4 v5 = ((const float4*)g_xw)[rb.y];
                float4 v6 = ((const float4*)g_xw)[rb.z];
                float4 v7 = ((const float4*)g_xw)[rb.w];
#define RED4(cidx, v) \
                asm volatile("red.global.add.v4.f32 [%0], {%1, %2, %3, %4};" \
                             :: "l"(&g_agg[4 * (cidx)]), "f"((v).x), "f"((v).y), "f"((v).z), "f"((v).w) \
                             : "memory")
                RED4(ca.x, v0); RED4(ca.y, v1); RED4(ca.z, v2); RED4(ca.w, v3);
                RED4(cb.x, v4); RED4(cb.y, v5); RED4(cb.z, v6); RED4(cb.w, v7);
            } else {
                for (int e = base; e < E; ++e) {
                    int r = ei[e], c = col[e];
                    float4 v = ((const float4*)g_xw)[r];
                    RED4(c, v);
                }
            }
#undef RED4
        }
    }
    gbar();

    // ===== Phase 4: score + top-k per (graph, column) =======================
    // Idle blocks (bid >= NJOBS) prefetch x into L2 for phase 5.
    if (bid >= NJOBS) {
        size_t bytes = (size_t)n * INCH * 4;
        int pb  = NB - NJOBS;
        int pbi = bid - NJOBS;
        const char* xb = (const char*)x;
        size_t step = (size_t)pb * NT * 128;
        for (size_t off = (size_t)(pbi * NT + tid) * 128; off < bytes; off += step)
            asm volatile("prefetch.global.L2 [%0];" :: "l"(xb + off));
    }
    for (int job = bid; job < NJOBS; job += NB) {
        int g = job >> 2;
        int c = job & 3;

        if (tid == 0) { s_p0 = NT; s_p1 = NT; s_prefix = 0u; }
        __syncthreads();
        int stride = (n + NT - 1) / NT;
        {
            int pos = tid * stride;
            int v = (pos < n) ? batch[pos] : 0x7fffffff;
            if (v >= g)     atomicMin(&s_p0, tid);
            if (v >= g + 1) atomicMin(&s_p1, tid);
        }
        __syncthreads();
        int t0 = s_p0, t1 = s_p1;
        __syncthreads();
        if (tid == 0) { s_p0 = n; s_p1 = n; }
        __syncthreads();
        {
            int lo0 = (t0 == 0) ? 0 : (t0 - 1) * stride + 1;
            int hi0 = min(t0 * stride, n - 1);
            for (int idx = lo0 + tid; idx <= hi0; idx += NT)
                if (batch[idx] >= g) atomicMin(&s_p0, idx);
            int lo1 = (t1 == 0) ? 0 : (t1 - 1) * stride + 1;
            int hi1 = min(t1 * stride, n - 1);
            for (int idx = lo1 + tid; idx <= hi1; idx += NT)
                if (batch[idx] >= g + 1) atomicMin(&s_p1, idx);
        }
        __syncthreads();
        int start = s_p0;
        int ng    = s_p1 - s_p0;
        if (ng < 0) ng = 0;
        int k     = (ng + 1) >> 1;        // ceil(0.5*ng)
        float bc  = bb[c];

        for (int t = tid; t < ng; t += NT) {
            size_t idx = (size_t)(start + t) * 4 + c;
            float d = g_dinv[start + t];
            float s = tanhf(d * (__ldcg(&g_agg[idx]) + g_xw[idx]) + bc);
            __stcg(&g_agg[idx], s);
            if (t < SORTN) {
                unsigned u = __float_as_uint(s);
                u = (u & 0x80000000u) ? ~u : (u | 0x80000000u);
                sm.tk.u[t] = ~u;
            }
        }
        if (tid == 0) s_target = k - 1;
        __syncthreads();

        if (ng <= SORTN) {
            unsigned done_mask = 0u;
#pragma unroll
            for (int pass = 0; pass < 4; ++pass) {
                int shift = 24 - 8 * pass;
                sm.tk.hist[tid] = 0;
                __syncthreads();
                unsigned pref = s_prefix;
                int tgt = s_target;
                for (int t = tid; t < ng; t += NT) {
                    unsigned u = sm.tk.u[t];
                    if ((u & done_mask) == pref)
                        atomicAdd(&sm.tk.hist[(u >> shift) & 255u], 1);
                }
                __syncthreads();
                int h    = sm.tk.hist[tid];
                int excl = scan256(h, tid, sm.tk.wsum);
                if (excl <= tgt && tgt < excl + h) {
                    s_prefix |= ((unsigned)tid) << shift;
                    s_target  = tgt - excl;
                }
                done_mask |= 0xFFu << shift;
                __syncthreads();
            }
            unsigned T = s_prefix;
            int r = s_target;
            int chunk = (ng + NT - 1) / NT;
            int lo = min(tid * chunk, ng);
            int hi = min(lo + chunk, ng);
            int cnt = 0;
            for (int t = lo; t < hi; ++t) cnt += (sm.tk.u[t] == T);
            int eqrank = scan256(cnt, tid, sm.tk.wsum);
            for (int t = lo; t < hi; ++t) {
                unsigned u = sm.tk.u[t];
                bool sel = (u < T) || (u == T && eqrank <= r);
                eqrank += (u == T);
                if (sel) atomicOr(&g_mask[start + t], 1 << c);
            }
        } else {
            for (int t = tid; t < ng; t += NT) {
                float st = __ldcg(&g_agg[(size_t)(start + t) * 4 + c]);
                int rank = 0;
                for (int j = 0; j < ng; ++j) {
                    float sj = __ldcg(&g_agg[(size_t)(start + j) * 4 + c]);
                    rank += (sj > st) || (sj == st && j < t);
                }
                if (rank < k) atomicOr(&g_mask[start + t], 1 << c);
            }
        }
        __syncthreads();
    }
    gbar();

    // ===== Phase 5: output (2 nodes/warp) ===================================
    for (int t = tid; t < CC * (INCH / 4); t += NT)
        sm.o.pe[t] = ((const float4*)pe)[t];
    __syncthreads();

    int outU = (n + 15) >> 4;             // 16 nodes per unit, 2 per warp
    for (int v = bid; v < outU; v += NB) {
        int base = v * 16 + warp * 2;
        int    mj[2];
        float4 sj[2];
        float4 xv[2][2];
#pragma unroll
        for (int j = 0; j < 2; ++j) {
            int node = (base + j < n) ? base + j : (n - 1);
            mj[j] = __ldcg(&g_mask[node]);
            sj[j] = __ldcg((const float4*)&g_agg[4 * node]);
            const float4* xr = (const float4*)(x + (size_t)node * INCH);
            xv[j][0] = __ldcs(&xr[lane]);
            xv[j][1] = __ldcs(&xr[lane + 32]);
        }
#pragma unroll
        for (int j = 0; j < 2; ++j) {
            if (base + j >= n) continue;
            int   m   = mj[j];
            float inv = 1.0f / (1.0f + (float)__popc(m & 0xF));
            float w0 = (m & 1) ? sj[j].x * inv : 0.f;
            float w1 = (m & 2) ? sj[j].y * inv : 0.f;
            float w2 = (m & 4) ? sj[j].z * inv : 0.f;
            float w3 = (m & 8) ? sj[j].w * inv : 0.f;
            float4* orow = (float4*)(out + (size_t)(base + j) * INCH);
#pragma unroll
            for (int it = 0; it < 2; ++it) {
                int k4 = lane + it * 32;
                float4 q  = xv[j][it];
                float4 p0 = sm.o.pe[0 * 64 + k4];
                float4 p1 = sm.o.pe[1 * 64 + k4];
                float4 p2 = sm.o.pe[2 * 64 + k4];
                float4 p3 = sm.o.pe[3 * 64 + k4];
                float4 o;
                o.x = q.x + w0 * p0.x + w1 * p1.x + w2 * p2.x + w3 * p3.x;
                o.y = q.y + w0 * p0.y + w1 * p1.y + w2 * p2.y + w3 * p3.y;
                o.z = q.z + w0 * p0.z + w1 * p1.z + w2 * p2.z + w3 * p3.z;
                o.w = q.w + w0 * p0.w + w1 * p1.w + w2 * p2.w + w3 * p3.w;
                __stcs(&orow[k4], o);
            }
        }
    }
}

// ---------------------------------------------------------------------------
extern "C" void kernel_launch(void* const* d_in, const int* in_sizes, int n_in,
                              void* d_out, int out_size) {
    const float* x     = (const float*)d_in[0];
    const int*   ei    = (const int*)  d_in[1];
    const int*   batch = (const int*)  d_in[2];
    const float* pe    = (const float*)d_in[3];
    const float* W     = (const float*)d_in[4];
    const float* b     = (const float*)d_in[5];
    float*       out   = (float*)d_out;

    int n = in_sizes[0] / INCH;
    int E = in_sizes[1] / 2;

    int dev = 0;
    cudaGetDevice(&dev);
    int smc = 0;
    if (cudaDeviceGetAttribute(&smc, cudaDevAttrMultiProcessorCount, dev)
            != cudaSuccess || smc <= 0)
        smc = 148;
    int NB = smc * OCC;                   // all CTAs co-resident (launch_bounds)

    k_fused<<<NB, NT>>>(x, ei, batch, pe, W, b, out, n, E);
}

// round 10
// speedup vs baseline: 1.0476x; 1.0476x over previous
#include <cuda_runtime.h>
#include <stdint.h>

#define CC     4
#define INCH   256
#define NT     256
#define SORTN  2048
#define NMAXN  100000
#define NJOBS  256                       // 64 graphs * 4 columns
#define OCC    3

// Scratch (device globals; no allocation allowed)
__device__ float g_xw[NMAXN * CC];
__device__ float g_agg[NMAXN * CC];
__device__ float g_deg[NMAXN];
__device__ float g_dinv[NMAXN];
__device__ int   g_mask[NMAXN];
__device__ unsigned g_bar_cnt;
__device__ volatile unsigned g_bar_gen;

struct TkS  { unsigned u[SORTN]; int hist[256]; int wsum[8]; };
struct XwS  { float pes[INCH]; float4 Wm[INCH]; };
struct OutS { float4 pe[CC * (INCH / 4)]; };
union SmemU { TkS tk; XwS xw; OutS o; };

__device__ __forceinline__ void gbar() {
    __threadfence();
    __syncthreads();
    if (threadIdx.x == 0) {
        unsigned gen = g_bar_gen;
        if (atomicAdd(&g_bar_cnt, 1u) == gridDim.x - 1u) {
            g_bar_cnt = 0u;
            __threadfence();
            g_bar_gen = gen + 1u;
        } else {
            while (g_bar_gen == gen) __nanosleep(32);
        }
    }
    __syncthreads();
}

__device__ __forceinline__ int scan256(int v, int tid, int* wsum) {
    int lane = tid & 31, wid = tid >> 5, orig = v;
#pragma unroll
    for (int o = 1; o < 32; o <<= 1) {
        int t = __shfl_up_sync(0xffffffffu, v, o);
        if (lane >= o) v += t;
    }
    if (lane == 31) wsum[wid] = v;
    __syncthreads();
    if (wid == 0 && lane < 8) {
        int w = wsum[lane];
#pragma unroll
        for (int o = 1; o < 8; o <<= 1) {
            int t = __shfl_up_sync(0xffu, w, o, 8);
            if (lane >= o) w += t;
        }
        wsum[lane] = w;
    }
    __syncthreads();
    return v + (wid ? wsum[wid - 1] : 0) - orig;
}

__global__ void __launch_bounds__(NT, OCC) k_fused(
    const float* __restrict__ x, const int* __restrict__ ei,
    const int* __restrict__ batch, const float* __restrict__ pe,
    const float* __restrict__ W, const float* __restrict__ bb,
    float* __restrict__ out, int n, int E) {
    __shared__ SmemU sm;
    __shared__ int s_p0, s_p1, s_target;
    __shared__ unsigned s_prefix;

    int tid  = threadIdx.x;
    int bid  = blockIdx.x;
    int NB   = gridDim.x;
    int warp = tid >> 5, lane = tid & 31;
    const int* col = ei + E;

    // ===== Phase 1: xw GEMV (4 nodes/warp) + degree atomics, block-stride ===
    for (int t = tid; t < INCH; t += NT) {
        sm.xw.pes[t] = pe[t] + pe[INCH + t] + pe[2 * INCH + t] + pe[3 * INCH + t];
        sm.xw.Wm[t]  = ((const float4*)W)[t];
    }
    __syncthreads();

    int xwU  = (n + 31) >> 5;             // 32 nodes per unit (4 per warp)
    int degU = (E + 1023) >> 10;          // 1024 edges per unit
    for (int v = bid; v < xwU + degU; v += NB) {
        if (v < xwU) {
            int base = v * 32 + warp * 4;
            float4 xv[4][2];
#pragma unroll
            for (int j = 0; j < 4; ++j) {
                int node = (base + j < n) ? base + j : (n - 1);
                const float4* xr = (const float4*)(x + (size_t)node * INCH);
                xv[j][0] = __ldcs(&xr[lane]);
                xv[j][1] = __ldcs(&xr[lane + 32]);
            }
#pragma unroll
            for (int j = 0; j < 4; ++j) {
                float a0 = 0.f, a1 = 0.f, a2 = 0.f, a3 = 0.f;
#pragma unroll
                for (int it = 0; it < 2; ++it) {
                    int k4 = lane + it * 32;
                    float4 q = xv[j][it];
                    int k = k4 * 4;
                    float x0 = q.x + sm.xw.pes[k + 0];
                    float x1 = q.y + sm.xw.pes[k + 1];
                    float x2 = q.z + sm.xw.pes[k + 2];
                    float x3 = q.w + sm.xw.pes[k + 3];
                    float4 w0 = sm.xw.Wm[k + 0], w1 = sm.xw.Wm[k + 1];
                    float4 w2 = sm.xw.Wm[k + 2], w3 = sm.xw.Wm[k + 3];
                    a0 += x0 * w0.x + x1 * w1.x + x2 * w2.x + x3 * w3.x;
                    a1 += x0 * w0.y + x1 * w1.y + x2 * w2.y + x3 * w3.y;
                    a2 += x0 * w0.z + x1 * w1.z + x2 * w2.z + x3 * w3.z;
                    a3 += x0 * w0.w + x1 * w1.w + x2 * w2.w + x3 * w3.w;
                }
#pragma unroll
                for (int o = 16; o; o >>= 1) {
                    a0 += __shfl_xor_sync(0xffffffffu, a0, o);
                    a1 += __shfl_xor_sync(0xffffffffu, a1, o);
                    a2 += __shfl_xor_sync(0xffffffffu, a2, o);
                    a3 += __shfl_xor_sync(0xffffffffu, a3, o);
                }
                if (lane == 0 && base + j < n) {
                    ((float4*)g_xw)[base + j]  = make_float4(a0, a1, a2, a3);
                    ((float4*)g_agg)[base + j] = make_float4(0.f, 0.f, 0.f, 0.f);
                    g_mask[base + j] = 0;
                }
            }
        } else {
            int d = v - xwU;
            int e = d * 1024 + tid;
#pragma unroll
            for (int it = 0; it < 4; ++it) {
                int ee = e + it * 256;
                if (ee < E) atomicAdd(&g_deg[__ldcs(&col[ee])], 1.0f);
            }
        }
    }
    gbar();

    // ===== Phase 2: prep ====================================================
    for (int i = bid * NT + tid; i < n; i += NB * NT) {
        float d = rsqrtf(g_deg[i] + 1.0f);
        g_deg[i]  = 0.0f;
        g_dinv[i] = d;
        float4 v = ((const float4*)g_xw)[i];
        v.x *= d; v.y *= d; v.z *= d; v.w *= d;
        ((float4*)g_xw)[i] = v;
    }
    gbar();

    // ===== Phase 3: edge aggregation ========================================
    {
        int eU = (E + 7) >> 3;
        for (int t = bid * NT + tid; t < eU; t += NB * NT) {
            int base = t * 8;
            if (base + 8 <= E) {
                int4 ra = __ldcs((const int4*)(ei + base));
                int4 rb = __ldcs((const int4*)(ei + base + 4));
                int4 ca = __ldcs((const int4*)(col + base));
                int4 cb = __ldcs((const int4*)(col + base + 4));
                float4 v0 = ((const float4*)g_xw)[ra.x];
                float4 v1 = ((const float4*)g_xw)[ra.y];
                float4 v2 = ((const float4*)g_xw)[ra.z];
                float4 v3 = ((const float4*)g_xw)[ra.w];
                float4 v4 = ((const float4*)g_xw)[rb.x];
                float4 v5 = ((const float4*)g_xw)[rb.y];
                float4 v6 = ((const float4*)g_xw)[rb.z];
                float4 v7 = ((const float4*)g_xw)[rb.w];
#define RED4(cidx, v) \
                asm volatile("red.global.add.v4.f32 [%0], {%1, %2, %3, %4};" \
                             :: "l"(&g_agg[4 * (cidx)]), "f"((v).x), "f"((v).y), "f"((v).z), "f"((v).w) \
                             : "memory")
                RED4(ca.x, v0); RED4(ca.y, v1); RED4(ca.z, v2); RED4(ca.w, v3);
                RED4(cb.x, v4); RED4(cb.y, v5); RED4(cb.z, v6); RED4(cb.w, v7);
            } else {
                for (int e = base; e < E; ++e) {
                    int r = ei[e], c = col[e];
                    float4 v = ((const float4*)g_xw)[r];
                    RED4(c, v);
                }
            }
#undef RED4
        }
    }
    gbar();

    // ===== Phase 4: score + top-k per (graph, column) =======================
    // Idle blocks prefetch the FIRST HALF of x into L2 (capped so it finishes
    // within topk's duration; full x would also thrash the ~120MB L2).
    if (bid >= NJOBS) {
        size_t halfBytes = ((size_t)n * INCH * 4) / 2;
        int pb  = NB - NJOBS;
        int pbi = bid - NJOBS;
        const char* xb = (const char*)x;
        size_t step = (size_t)pb * NT * 128;
        for (size_t off = (size_t)(pbi * NT + tid) * 128; off < halfBytes; off += step)
            asm volatile("prefetch.global.L2 [%0];" :: "l"(xb + off));
    }
    for (int job = bid; job < NJOBS; job += NB) {
        int g = job >> 2;
        int c = job & 3;

        if (tid == 0) { s_p0 = NT; s_p1 = NT; s_prefix = 0u; }
        __syncthreads();
        int stride = (n + NT - 1) / NT;
        {
            int pos = tid * stride;
            int v = (pos < n) ? batch[pos] : 0x7fffffff;
            if (v >= g)     atomicMin(&s_p0, tid);
            if (v >= g + 1) atomicMin(&s_p1, tid);
        }
        __syncthreads();
        int t0 = s_p0, t1 = s_p1;
        __syncthreads();
        if (tid == 0) { s_p0 = n; s_p1 = n; }
        __syncthreads();
        {
            int lo0 = (t0 == 0) ? 0 : (t0 - 1) * stride + 1;
            int hi0 = min(t0 * stride, n - 1);
            for (int idx = lo0 + tid; idx <= hi0; idx += NT)
                if (batch[idx] >= g) atomicMin(&s_p0, idx);
            int lo1 = (t1 == 0) ? 0 : (t1 - 1) * stride + 1;
            int hi1 = min(t1 * stride, n - 1);
            for (int idx = lo1 + tid; idx <= hi1; idx += NT)
                if (batch[idx] >= g + 1) atomicMin(&s_p1, idx);
        }
        __syncthreads();
        int start = s_p0;
        int ng    = s_p1 - s_p0;
        if (ng < 0) ng = 0;
        int k     = (ng + 1) >> 1;        // ceil(0.5*ng)
        float bc  = bb[c];

        for (int t = tid; t < ng; t += NT) {
            size_t idx = (size_t)(start + t) * 4 + c;
            float d = g_dinv[start + t];
            float s = tanhf(d * (__ldcg(&g_agg[idx]) + g_xw[idx]) + bc);
            __stcg(&g_agg[idx], s);
            if (t < SORTN) {
                unsigned u = __float_as_uint(s);
                u = (u & 0x80000000u) ? ~u : (u | 0x80000000u);
                sm.tk.u[t] = ~u;
            }
        }
        if (tid == 0) s_target = k - 1;
        __syncthreads();

        if (ng <= SORTN) {
            unsigned done_mask = 0u;
#pragma unroll
            for (int pass = 0; pass < 4; ++pass) {
                int shift = 24 - 8 * pass;
                sm.tk.hist[tid] = 0;
                __syncthreads();
                unsigned pref = s_prefix;
                int tgt = s_target;
                for (int t = tid; t < ng; t += NT) {
                    unsigned u = sm.tk.u[t];
                    if ((u & done_mask) == pref)
                        atomicAdd(&sm.tk.hist[(u >> shift) & 255u], 1);
                }
                __syncthreads();
                int h    = sm.tk.hist[tid];
                int excl = scan256(h, tid, sm.tk.wsum);
                if (excl <= tgt && tgt < excl + h) {
                    s_prefix |= ((unsigned)tid) << shift;
                    s_target  = tgt - excl;
                }
                done_mask |= 0xFFu << shift;
                __syncthreads();
            }
            unsigned T = s_prefix;
            int r = s_target;
            int chunk = (ng + NT - 1) / NT;
            int lo = min(tid * chunk, ng);
            int hi = min(lo + chunk, ng);
            int cnt = 0;
            for (int t = lo; t < hi; ++t) cnt += (sm.tk.u[t] == T);
            int eqrank = scan256(cnt, tid, sm.tk.wsum);
            for (int t = lo; t < hi; ++t) {
                unsigned u = sm.tk.u[t];
                bool sel = (u < T) || (u == T && eqrank <= r);
                eqrank += (u == T);
                if (sel) atomicOr(&g_mask[start + t], 1 << c);
            }
        } else {
            for (int t = tid; t < ng; t += NT) {
                float st = __ldcg(&g_agg[(size_t)(start + t) * 4 + c]);
                int rank = 0;
                for (int j = 0; j < ng; ++j) {
                    float sj = __ldcg(&g_agg[(size_t)(start + j) * 4 + c]);
                    rank += (sj > st) || (sj == st && j < t);
                }
                if (rank < k) atomicOr(&g_mask[start + t], 1 << c);
            }
        }
        __syncthreads();
    }
    gbar();

    // ===== Phase 5: output (4 nodes/warp) ===================================
    for (int t = tid; t < CC * (INCH / 4); t += NT)
        sm.o.pe[t] = ((const float4*)pe)[t];
    __syncthreads();

    int outU = (n + 31) >> 5;             // 32 nodes per unit, 4 per warp
    for (int v = bid; v < outU; v += NB) {
        int base = v * 32 + warp * 4;
        int    mj[4];
        float4 sj[4];
        float4 xv[4][2];
#pragma unroll
        for (int j = 0; j < 4; ++j) {
            int node = (base + j < n) ? base + j : (n - 1);
            mj[j] = __ldcg(&g_mask[node]);
            sj[j] = __ldcg((const float4*)&g_agg[4 * node]);
            const float4* xr = (const float4*)(x + (size_t)node * INCH);
            xv[j][0] = __ldcs(&xr[lane]);
            xv[j][1] = __ldcs(&xr[lane + 32]);
        }
#pragma unroll
        for (int j = 0; j < 4; ++j) {
            if (base + j >= n) continue;
            int   m   = mj[j];
            float inv = 1.0f / (1.0f + (float)__popc(m & 0xF));
            float w0 = (m & 1) ? sj[j].x * inv : 0.f;
            float w1 = (m & 2) ? sj[j].y * inv : 0.f;
            float w2 = (m & 4) ? sj[j].z * inv : 0.f;
            float w3 = (m & 8) ? sj[j].w * inv : 0.f;
            float4* orow = (float4*)(out + (size_t)(base + j) * INCH);
#pragma unroll
            for (int it = 0; it < 2; ++it) {
                int k4 = lane + it * 32;
                float4 q  = xv[j][it];
                float4 p0 = sm.o.pe[0 * 64 + k4];
                float4 p1 = sm.o.pe[1 * 64 + k4];
                float4 p2 = sm.o.pe[2 * 64 + k4];
                float4 p3 = sm.o.pe[3 * 64 + k4];
                float4 o;
                o.x = q.x + w0 * p0.x + w1 * p1.x + w2 * p2.x + w3 * p3.x;
                o.y = q.y + w0 * p0.y + w1 * p1.y + w2 * p2.y + w3 * p3.y;
                o.z = q.z + w0 * p0.z + w1 * p1.z + w2 * p2.z + w3 * p3.z;
                o.w = q.w + w0 * p0.w + w1 * p1.w + w2 * p2.w + w3 * p3.w;
                __stcs(&orow[k4], o);
            }
        }
    }
}

// ---------------------------------------------------------------------------
extern "C" void kernel_launch(void* const* d_in, const int* in_sizes, int n_in,
                              void* d_out, int out_size) {
    const float* x     = (const float*)d_in[0];
    const int*   ei    = (const int*)  d_in[1];
    const int*   batch = (const int*)  d_in[2];
    const float* pe    = (const float*)d_in[3];
    const float* W     = (const float*)d_in[4];
    const float* b     = (const float*)d_in[5];
    float*       out   = (float*)d_out;

    int n = in_sizes[0] / INCH;
    int E = in_sizes[1] / 2;

    int dev = 0;
    cudaGetDevice(&dev);
    int smc = 0;
    if (cudaDeviceGetAttribute(&smc, cudaDevAttrMultiProcessorCount, dev)
            != cudaSuccess || smc <= 0)
        smc = 148;
    int NB = smc * OCC;                   // all CTAs co-resident (launch_bounds)

    k_fused<<<NB, NT>>>(x, ei, batch, pe, W, b, out, n, E);
}

// round 11
// speedup vs baseline: 1.0644x; 1.0161x over previous
#include <cuda_runtime.h>
#include <stdint.h>

#define CC     4
#define INCH   256
#define NT     256
#define SORTN  2048
#define NMAXN  100000
#define NJOBS  256                       // 64 graphs * 4 columns
#define OCC    3

// Scratch (device globals; no allocation allowed)
__device__ float g_xw[NMAXN * CC];
__device__ float g_agg[NMAXN * CC];
__device__ float g_deg[NMAXN];
__device__ float g_dinv[NMAXN];
__device__ int   g_mask[NMAXN];
__device__ unsigned g_bar_cnt;
__device__ volatile unsigned g_bar_gen;

struct TkS  { unsigned u[SORTN]; int hist[256]; int wsum[8]; };
struct XwS  { float pes[INCH]; float4 Wm[INCH]; };
struct OutS { float4 pe[CC * (INCH / 4)]; };
union SmemU { TkS tk; XwS xw; OutS o; };

__device__ __forceinline__ void gbar() {
    __threadfence();
    __syncthreads();
    if (threadIdx.x == 0) {
        unsigned gen = g_bar_gen;
        if (atomicAdd(&g_bar_cnt, 1u) == gridDim.x - 1u) {
            g_bar_cnt = 0u;
            __threadfence();
            g_bar_gen = gen + 1u;
        } else {
            while (g_bar_gen == gen) __nanosleep(32);
        }
    }
    __syncthreads();
}

__device__ __forceinline__ int scan256(int v, int tid, int* wsum) {
    int lane = tid & 31, wid = tid >> 5, orig = v;
#pragma unroll
    for (int o = 1; o < 32; o <<= 1) {
        int t = __shfl_up_sync(0xffffffffu, v, o);
        if (lane >= o) v += t;
    }
    if (lane == 31) wsum[wid] = v;
    __syncthreads();
    if (wid == 0 && lane < 8) {
        int w = wsum[lane];
#pragma unroll
        for (int o = 1; o < 8; o <<= 1) {
            int t = __shfl_up_sync(0xffu, w, o, 8);
            if (lane >= o) w += t;
        }
        wsum[lane] = w;
    }
    __syncthreads();
    return v + (wid ? wsum[wid - 1] : 0) - orig;
}

__global__ void __launch_bounds__(NT, OCC) k_fused(
    const float* __restrict__ x, const int* __restrict__ ei,
    const int* __restrict__ batch, const float* __restrict__ pe,
    const float* __restrict__ W, const float* __restrict__ bb,
    float* __restrict__ out, int n, int E) {
    __shared__ SmemU sm;
    __shared__ int s_p0, s_p1, s_target;
    __shared__ unsigned s_prefix;

    int tid  = threadIdx.x;
    int bid  = blockIdx.x;
    int NB   = gridDim.x;
    int warp = tid >> 5, lane = tid & 31;
    const int* col = ei + E;

    // ===== Phase 1: xw GEMV (4 nodes/warp) + degree atomics, block-stride ===
    // x is read with NORMAL caching policy: x (102MB) fits B200's ~126MB L2,
    // intermediate phases touch only ~30MB, so phase 5 re-reads hit L2.
    for (int t = tid; t < INCH; t += NT) {
        sm.xw.pes[t] = pe[t] + pe[INCH + t] + pe[2 * INCH + t] + pe[3 * INCH + t];
        sm.xw.Wm[t]  = ((const float4*)W)[t];
    }
    __syncthreads();

    int xwU  = (n + 31) >> 5;             // 32 nodes per unit (4 per warp)
    int degU = (E + 1023) >> 10;          // 1024 edges per unit
    for (int v = bid; v < xwU + degU; v += NB) {
        if (v < xwU) {
            int base = v * 32 + warp * 4;
            float4 xv[4][2];
#pragma unroll
            for (int j = 0; j < 4; ++j) {
                int node = (base + j < n) ? base + j : (n - 1);
                const float4* xr = (const float4*)(x + (size_t)node * INCH);
                xv[j][0] = xr[lane];          // keep in L2 for phase 5
                xv[j][1] = xr[lane + 32];
            }
#pragma unroll
            for (int j = 0; j < 4; ++j) {
                float a0 = 0.f, a1 = 0.f, a2 = 0.f, a3 = 0.f;
#pragma unroll
                for (int it = 0; it < 2; ++it) {
                    int k4 = lane + it * 32;
                    float4 q = xv[j][it];
                    int k = k4 * 4;
                    float x0 = q.x + sm.xw.pes[k + 0];
                    float x1 = q.y + sm.xw.pes[k + 1];
                    float x2 = q.z + sm.xw.pes[k + 2];
                    float x3 = q.w + sm.xw.pes[k + 3];
                    float4 w0 = sm.xw.Wm[k + 0], w1 = sm.xw.Wm[k + 1];
                    float4 w2 = sm.xw.Wm[k + 2], w3 = sm.xw.Wm[k + 3];
                    a0 += x0 * w0.x + x1 * w1.x + x2 * w2.x + x3 * w3.x;
                    a1 += x0 * w0.y + x1 * w1.y + x2 * w2.y + x3 * w3.y;
                    a2 += x0 * w0.z + x1 * w1.z + x2 * w2.z + x3 * w3.z;
                    a3 += x0 * w0.w + x1 * w1.w + x2 * w2.w + x3 * w3.w;
                }
#pragma unroll
                for (int o = 16; o; o >>= 1) {
                    a0 += __shfl_xor_sync(0xffffffffu, a0, o);
                    a1 += __shfl_xor_sync(0xffffffffu, a1, o);
                    a2 += __shfl_xor_sync(0xffffffffu, a2, o);
                    a3 += __shfl_xor_sync(0xffffffffu, a3, o);
                }
                if (lane == 0 && base + j < n) {
                    ((float4*)g_xw)[base + j]  = make_float4(a0, a1, a2, a3);
                    ((float4*)g_agg)[base + j] = make_float4(0.f, 0.f, 0.f, 0.f);
                    g_mask[base + j] = 0;
                }
            }
        } else {
            int d = v - xwU;
            int e = d * 1024 + tid;
#pragma unroll
            for (int it = 0; it < 4; ++it) {
                int ee = e + it * 256;
                if (ee < E) atomicAdd(&g_deg[__ldcs(&col[ee])], 1.0f);
            }
        }
    }
    gbar();

    // ===== Phase 2: prep ====================================================
    for (int i = bid * NT + tid; i < n; i += NB * NT) {
        float d = rsqrtf(g_deg[i] + 1.0f);
        g_deg[i]  = 0.0f;
        g_dinv[i] = d;
        float4 v = ((const float4*)g_xw)[i];
        v.x *= d; v.y *= d; v.z *= d; v.w *= d;
        ((float4*)g_xw)[i] = v;
    }
    gbar();

    // ===== Phase 3: edge aggregation ========================================
    {
        int eU = (E + 7) >> 3;
        for (int t = bid * NT + tid; t < eU; t += NB * NT) {
            int base = t * 8;
            if (base + 8 <= E) {
                int4 ra = __ldcs((const int4*)(ei + base));
                int4 rb = __ldcs((const int4*)(ei + base + 4));
                int4 ca = __ldcs((const int4*)(col + base));
                int4 cb = __ldcs((const int4*)(col + base + 4));
                float4 v0 = ((const float4*)g_xw)[ra.x];
                float4 v1 = ((const float4*)g_xw)[ra.y];
                float4 v2 = ((const float4*)g_xw)[ra.z];
                float4 v3 = ((const float4*)g_xw)[ra.w];
                float4 v4 = ((const float4*)g_xw)[rb.x];
                float4 v5 = ((const float4*)g_xw)[rb.y];
                float4 v6 = ((const float4*)g_xw)[rb.z];
                float4 v7 = ((const float4*)g_xw)[rb.w];
#define RED4(cidx, v) \
                asm volatile("red.global.add.v4.f32 [%0], {%1, %2, %3, %4};" \
                             :: "l"(&g_agg[4 * (cidx)]), "f"((v).x), "f"((v).y), "f"((v).z), "f"((v).w) \
                             : "memory")
                RED4(ca.x, v0); RED4(ca.y, v1); RED4(ca.z, v2); RED4(ca.w, v3);
                RED4(cb.x, v4); RED4(cb.y, v5); RED4(cb.z, v6); RED4(cb.w, v7);
            } else {
                for (int e = base; e < E; ++e) {
                    int r = ei[e], c = col[e];
                    float4 v = ((const float4*)g_xw)[r];
                    RED4(c, v);
                }
            }
#undef RED4
        }
    }
    gbar();

    // ===== Phase 4: score + top-k per (graph, column) =======================
    for (int job = bid; job < NJOBS; job += NB) {
        int g = job >> 2;
        int c = job & 3;

        if (tid == 0) { s_p0 = NT; s_p1 = NT; s_prefix = 0u; }
        __syncthreads();
        int stride = (n + NT - 1) / NT;
        {
            int pos = tid * stride;
            int v = (pos < n) ? batch[pos] : 0x7fffffff;
            if (v >= g)     atomicMin(&s_p0, tid);
            if (v >= g + 1) atomicMin(&s_p1, tid);
        }
        __syncthreads();
        int t0 = s_p0, t1 = s_p1;
        __syncthreads();
        if (tid == 0) { s_p0 = n; s_p1 = n; }
        __syncthreads();
        {
            int lo0 = (t0 == 0) ? 0 : (t0 - 1) * stride + 1;
            int hi0 = min(t0 * stride, n - 1);
            for (int idx = lo0 + tid; idx <= hi0; idx += NT)
                if (batch[idx] >= g) atomicMin(&s_p0, idx);
            int lo1 = (t1 == 0) ? 0 : (t1 - 1) * stride + 1;
            int hi1 = min(t1 * stride, n - 1);
            for (int idx = lo1 + tid; idx <= hi1; idx += NT)
                if (batch[idx] >= g + 1) atomicMin(&s_p1, idx);
        }
        __syncthreads();
        int start = s_p0;
        int ng    = s_p1 - s_p0;
        if (ng < 0) ng = 0;
        int k     = (ng + 1) >> 1;        // ceil(0.5*ng)
        float bc  = bb[c];

        for (int t = tid; t < ng; t += NT) {
            size_t idx = (size_t)(start + t) * 4 + c;
            float d = g_dinv[start + t];
            float s = tanhf(d * (__ldcg(&g_agg[idx]) + g_xw[idx]) + bc);
            __stcg(&g_agg[idx], s);
            if (t < SORTN) {
                unsigned u = __float_as_uint(s);
                u = (u & 0x80000000u) ? ~u : (u | 0x80000000u);
                sm.tk.u[t] = ~u;
            }
        }
        if (tid == 0) s_target = k - 1;
        __syncthreads();

        if (ng <= SORTN) {
            unsigned done_mask = 0u;
#pragma unroll
            for (int pass = 0; pass < 4; ++pass) {
                int shift = 24 - 8 * pass;
                sm.tk.hist[tid] = 0;
                __syncthreads();
                unsigned pref = s_prefix;
                int tgt = s_target;
                for (int t = tid; t < ng; t += NT) {
                    unsigned u = sm.tk.u[t];
                    if ((u & done_mask) == pref)
                        atomicAdd(&sm.tk.hist[(u >> shift) & 255u], 1);
                }
                __syncthreads();
                int h    = sm.tk.hist[tid];
                int excl = scan256(h, tid, sm.tk.wsum);
                if (excl <= tgt && tgt < excl + h) {
                    s_prefix |= ((unsigned)tid) << shift;
                    s_target  = tgt - excl;
                }
                done_mask |= 0xFFu << shift;
                __syncthreads();
            }
            unsigned T = s_prefix;
            int r = s_target;
            int chunk = (ng + NT - 1) / NT;
            int lo = min(tid * chunk, ng);
            int hi = min(lo + chunk, ng);
            int cnt = 0;
            for (int t = lo; t < hi; ++t) cnt += (sm.tk.u[t] == T);
            int eqrank = scan256(cnt, tid, sm.tk.wsum);
            for (int t = lo; t < hi; ++t) {
                unsigned u = sm.tk.u[t];
                bool sel = (u < T) || (u == T && eqrank <= r);
                eqrank += (u == T);
                if (sel) atomicOr(&g_mask[start + t], 1 << c);
            }
        } else {
            for (int t = tid; t < ng; t += NT) {
                float st = __ldcg(&g_agg[(size_t)(start + t) * 4 + c]);
                int rank = 0;
                for (int j = 0; j < ng; ++j) {
                    float sj = __ldcg(&g_agg[(size_t)(start + j) * 4 + c]);
                    rank += (sj > st) || (sj == st && j < t);
                }
                if (rank < k) atomicOr(&g_mask[start + t], 1 << c);
            }
        }
        __syncthreads();
    }
    gbar();

    // ===== Phase 5: output (4 nodes/warp) ===================================
    // x reads: .cs (last use, evict-first); out stores: .cs (don't evict x).
    for (int t = tid; t < CC * (INCH / 4); t += NT)
        sm.o.pe[t] = ((const float4*)pe)[t];
    __syncthreads();

    int outU = (n + 31) >> 5;             // 32 nodes per unit, 4 per warp
    for (int v = bid; v < outU; v += NB) {
        int base = v * 32 + warp * 4;
        int    mj[4];
        float4 sj[4];
        float4 xv[4][2];
#pragma unroll
        for (int j = 0; j < 4; ++j) {
            int node = (base + j < n) ? base + j : (n - 1);
            mj[j] = __ldcg(&g_mask[node]);
            sj[j] = __ldcg((const float4*)&g_agg[4 * node]);
            const float4* xr = (const float4*)(x + (size_t)node * INCH);
            xv[j][0] = __ldcs(&xr[lane]);
            xv[j][1] = __ldcs(&xr[lane + 32]);
        }
#pragma unroll
        for (int j = 0; j < 4; ++j) {
            if (base + j >= n) continue;
            int   m   = mj[j];
            float inv = 1.0f / (1.0f + (float)__popc(m & 0xF));
            float w0 = (m & 1) ? sj[j].x * inv : 0.f;
            float w1 = (m & 2) ? sj[j].y * inv : 0.f;
            float w2 = (m & 4) ? sj[j].z * inv : 0.f;
            float w3 = (m & 8) ? sj[j].w * inv : 0.f;
            float4* orow = (float4*)(out + (size_t)(base + j) * INCH);
#pragma unroll
            for (int it = 0; it < 2; ++it) {
                int k4 = lane + it * 32;
                float4 q  = xv[j][it];
                float4 p0 = sm.o.pe[0 * 64 + k4];
                float4 p1 = sm.o.pe[1 * 64 + k4];
                float4 p2 = sm.o.pe[2 * 64 + k4];
                float4 p3 = sm.o.pe[3 * 64 + k4];
                float4 o;
                o.x = q.x + w0 * p0.x + w1 * p1.x + w2 * p2.x + w3 * p3.x;
                o.y = q.y + w0 * p0.y + w1 * p1.y + w2 * p2.y + w3 * p3.y;
                o.z = q.z + w0 * p0.z + w1 * p1.z + w2 * p2.z + w3 * p3.z;
                o.w = q.w + w0 * p0.w + w1 * p1.w + w2 * p2.w + w3 * p3.w;
                __stcs(&orow[k4], o);
            }
        }
    }
}

// ---------------------------------------------------------------------------
extern "C" void kernel_launch(void* const* d_in, const int* in_sizes, int n_in,
                              void* d_out, int out_size) {
    const float* x     = (const float*)d_in[0];
    const int*   ei    = (const int*)  d_in[1];
    const int*   batch = (const int*)  d_in[2];
    const float* pe    = (const float*)d_in[3];
    const float* W     = (const float*)d_in[4];
    const float* b     = (const float*)d_in[5];
    float*       out   = (float*)d_out;

    int n = in_sizes[0] / INCH;
    int E = in_sizes[1] / 2;

    int dev = 0;
    cudaGetDevice(&dev);
    int smc = 0;
    if (cudaDeviceGetAttribute(&smc, cudaDevAttrMultiProcessorCount, dev)
            != cudaSuccess || smc <= 0)
        smc = 148;
    int NB = smc * OCC;                   // all CTAs co-resident (launch_bounds)

    k_fused<<<NB, NT>>>(x, ei, batch, pe, W, b, out, n, E);
}